// round 2
// baseline (speedup 1.0000x reference)
#include <cuda_runtime.h>

typedef unsigned long long u64;

#define NP 64
#define NCOLS 500000
#define NCG   (NCOLS / 16)        /* 31250 column-groups of 16 cols */
#define RS    (NCOLS / 4)         /* row stride in ulonglong2 units  */
#define NANG 2016

// RT[r*64 + i] = mus[i] * R[i][r]  (R = product of Givens rotations)
__device__ float d_RT[NP * NP];

// ---------------------------------------------------------------------------
// Kernel 1: build the 64x64 combined rotation+scale matrix, fully in registers.
// Thread j owns column j of M (64 floats in regs; loops fully unrolled so all
// register indices are static). Critical chain: one FFMA per rotation.
// ---------------------------------------------------------------------------
__global__ void build_R_kernel(const float* __restrict__ angles,
                               const float* __restrict__ mus) {
    __shared__ float2 cs[NANG];
    const int j = threadIdx.x;

    for (int k = j; k < NANG; k += NP) {
        float s, c;
        sincosf(angles[k], &s, &c);
        cs[k] = make_float2(c, s);
    }
    __syncthreads();

    float m[NP];
    #pragma unroll
    for (int i = 0; i < NP; i++) m[i] = (i == j) ? 1.0f : 0.0f;

    int k = 0;
    #pragma unroll
    for (int it = 0; it < NP - 1; it++) {
        #pragma unroll
        for (int ib = it + 1; ib < NP; ib++, k++) {
            float2 c_s = cs[k];
            float vt = m[it], vb = m[ib];
            m[it] = c_s.x * vt - c_s.y * vb;   // vt' = c*vt - s*vb
            m[ib] = c_s.y * vt + c_s.x * vb;   // vb' = s*vt + c*vb
        }
    }
    // thread j holds column j of R -> row j of RT (RT[j][i] = R[i][j]*mus[i])
    #pragma unroll
    for (int i = 0; i < NP; i++)
        d_RT[j * NP + i] = m[i] * mus[i];
}

// ---------------------------------------------------------------------------
// Kernel 2: Y = M @ X. Thread tile: 8 output rows x 16 columns.
// Per input row r: 4 LDS.128 (R, broadcast) + 4 LDG.128 (X) -> 64 FFMA2.
// All 8 row-group warps in a block read the same X addresses -> L1 reuse.
// ---------------------------------------------------------------------------
__device__ __forceinline__ void fma2(u64& d, u64 a, u64 b) {
    asm("fma.rn.f32x2 %0, %1, %2, %0;" : "+l"(d) : "l"(a), "l"(b));
}
__device__ __forceinline__ u64 dup2(float v) {
    u64 r;
    asm("mov.b64 %0, {%1, %1};" : "=l"(r) : "r"(__float_as_uint(v)));
    return r;
}

__global__ void __launch_bounds__(256, 1)
gemm_kernel(const float* __restrict__ X, float* __restrict__ out) {
    __shared__ __align__(16) u64 sR[NP * NP];   // duplicated (v,v) pairs, 32 KB

    const int tid = threadIdx.x;
    const float4* R4 = (const float4*)d_RT;
    for (int t = tid; t < NP * NP / 4; t += 256) {
        float4 v = R4[t];
        sR[t * 4 + 0] = dup2(v.x);
        sR[t * 4 + 1] = dup2(v.y);
        sR[t * 4 + 2] = dup2(v.z);
        sR[t * 4 + 3] = dup2(v.w);
    }
    __syncthreads();

    const int  cg  = tid & 31;                 // column-group within block
    const int  rg  = tid >> 5;                 // row-group (warp id) 0..7
    const int  cgg = blockIdx.x * 32 + cg;     // global column-group
    const bool active = (cgg < NCG);
    const int  col0   = (active ? cgg : (NCG - 1)) * 16;

    const ulonglong2* Xp  = ((const ulonglong2*)X) + (col0 >> 2);
    const ulonglong2* sR2 = (const ulonglong2*)sR;
    const int rb = rg * 4;                     // R offset for this row-group

    u64 acc[8][8];
    #pragma unroll
    for (int il = 0; il < 8; il++)
        #pragma unroll
        for (int c = 0; c < 8; c++) acc[il][c] = 0ULL;

    ulonglong2 xa[4], xb[4];
    #pragma unroll
    for (int q = 0; q < 4; q++) xa[q] = Xp[q];

    #pragma unroll 1
    for (int r = 0; r < NP; r += 2) {
        // prefetch row r+1
        #pragma unroll
        for (int q = 0; q < 4; q++) xb[q] = Xp[(r + 1) * RS + q];
        {   // compute row r
            ulonglong2 rv[4];
            #pragma unroll
            for (int u = 0; u < 4; u++) rv[u] = sR2[r * 32 + rb + u];
            #pragma unroll
            for (int il = 0; il < 8; il++) {
                u64 Rd = (il & 1) ? rv[il >> 1].y : rv[il >> 1].x;
                #pragma unroll
                for (int q = 0; q < 4; q++) {
                    fma2(acc[il][2 * q + 0], Rd, xa[q].x);
                    fma2(acc[il][2 * q + 1], Rd, xa[q].y);
                }
            }
        }
        // prefetch row r+2
        if (r + 2 < NP) {
            #pragma unroll
            for (int q = 0; q < 4; q++) xa[q] = Xp[(r + 2) * RS + q];
        }
        {   // compute row r+1
            ulonglong2 rv[4];
            #pragma unroll
            for (int u = 0; u < 4; u++) rv[u] = sR2[(r + 1) * 32 + rb + u];
            #pragma unroll
            for (int il = 0; il < 8; il++) {
                u64 Rd = (il & 1) ? rv[il >> 1].y : rv[il >> 1].x;
                #pragma unroll
                for (int q = 0; q < 4; q++) {
                    fma2(acc[il][2 * q + 0], Rd, xb[q].x);
                    fma2(acc[il][2 * q + 1], Rd, xb[q].y);
                }
            }
        }
    }

    if (active) {
        #pragma unroll
        for (int il = 0; il < 8; il++) {
            const int i = rg * 8 + il;
            ulonglong2* Ov = (ulonglong2*)(out + (size_t)i * NCOLS + col0);
            #pragma unroll
            for (int q = 0; q < 4; q++) {
                ulonglong2 v;
                v.x = acc[il][2 * q + 0];
                v.y = acc[il][2 * q + 1];
                Ov[q] = v;
            }
        }
    }
}

// ---------------------------------------------------------------------------
extern "C" void kernel_launch(void* const* d_in, const int* in_sizes, int n_in,
                              void* d_out, int out_size) {
    const float* X      = (const float*)d_in[0];
    const float* angles = (const float*)d_in[1];
    const float* mus    = (const float*)d_in[2];
    float*       out    = (float*)d_out;

    build_R_kernel<<<1, NP>>>(angles, mus);
    const int grid = (NCG + 31) / 32;   // 977 blocks of 256 threads
    gemm_kernel<<<grid, 256>>>(X, out);
}

// round 3
// speedup vs baseline: 1.2083x; 1.2083x over previous
#include <cuda_runtime.h>

typedef unsigned long long u64;

#define NP 64
#define NCOLS 500000
#define BCOLS 256                         /* cols per block */
#define NB    ((NCOLS + BCOLS - 1) / BCOLS)   /* 1954 blocks */
#define NANG 2016

// RT[r*64 + i] = mus[i] * R[i][r]  (R = product of Givens rotations)
__device__ float d_RT[NP * NP];

// ---------------------------------------------------------------------------
// Kernel 1: build the 64x64 combined rotation+scale matrix, fully in registers.
// Thread j owns column j of M; loops fully unrolled -> static register indices.
// Critical chain: ~one FFMA (4 cyc) per rotation = ~8k cycles.
// ---------------------------------------------------------------------------
__global__ void __launch_bounds__(64)
build_R_kernel(const float* __restrict__ angles, const float* __restrict__ mus) {
    __shared__ float2 cs[NANG];
    const int j = threadIdx.x;

    for (int k = j; k < NANG; k += NP) {
        float s, c;
        sincosf(angles[k], &s, &c);
        cs[k] = make_float2(c, s);
    }
    __syncthreads();

    float m[NP];
    #pragma unroll
    for (int i = 0; i < NP; i++) m[i] = (i == j) ? 1.0f : 0.0f;

    int k = 0;
    #pragma unroll
    for (int it = 0; it < NP - 1; it++) {
        #pragma unroll
        for (int ib = it + 1; ib < NP; ib++, k++) {
            float2 c_s = cs[k];
            float vt = m[it], vb = m[ib];
            m[it] = c_s.x * vt - c_s.y * vb;    // vt' = c*vt - s*vb
            m[ib] = c_s.y * vt + c_s.x * vb;    // vb' = s*vt + c*vb
        }
    }
    #pragma unroll
    for (int i = 0; i < NP; i++)
        d_RT[j * NP + i] = m[i] * mus[i];
}

// ---------------------------------------------------------------------------
// Kernel 2: Y = M @ X.  Block: 64 rows x 256 cols, 8 warps, 2 blocks/SM.
// Thread: 8 rows x 8 cols (two 4-col groups 128 apart -> coalesced LDG.128).
// Per K: 2 LDG.128 (X) + 4 LDS.128 (R broadcast) -> 32 FFMA2.
// ---------------------------------------------------------------------------
__device__ __forceinline__ void fma2(u64& d, u64 a, u64 b) {
    asm("fma.rn.f32x2 %0, %1, %2, %0;" : "+l"(d) : "l"(a), "l"(b));
}
__device__ __forceinline__ u64 dup2(float v) {
    u64 r;
    asm("mov.b64 %0, {%1, %1};" : "=l"(r) : "r"(__float_as_uint(v)));
    return r;
}

__global__ void __launch_bounds__(256, 2)
gemm_kernel(const float* __restrict__ X, float* __restrict__ out) {
    __shared__ __align__(16) u64 sR[NP * NP];   // duplicated (v,v) pairs, 32 KB

    const int tid = threadIdx.x;
    const float4* R4 = (const float4*)d_RT;
    for (int t = tid; t < NP * NP / 4; t += 256) {
        float4 v = R4[t];
        sR[t * 4 + 0] = dup2(v.x);
        sR[t * 4 + 1] = dup2(v.y);
        sR[t * 4 + 2] = dup2(v.z);
        sR[t * 4 + 3] = dup2(v.w);
    }
    __syncthreads();

    const int lane = tid & 31;
    const int wid  = tid >> 5;                 // row-group: rows wid*8 .. +8
    const int colA = blockIdx.x * BCOLS + lane * 4;
    const int colB = colA + 128;
    const bool actA = (colA < NCOLS);
    const bool actB = (colB < NCOLS);
    const int colAc = actA ? colA : (NCOLS - 4);
    const int colBc = actB ? colB : (NCOLS - 4);

    const char* XA = (const char*)(X + colAc);
    const char* XB = (const char*)(X + colBc);
    const size_t rowb = (size_t)NCOLS * 4;     // row stride in bytes
    const ulonglong2* sR2 = (const ulonglong2*)sR;
    const int rbase = wid * 4;

    u64 aA[8][2], aB[8][2];
    #pragma unroll
    for (int il = 0; il < 8; il++) {
        aA[il][0] = aA[il][1] = 0ULL;
        aB[il][0] = aB[il][1] = 0ULL;
    }

    // software pipeline: depth-2 X prefetch
    ulonglong2 xa[2], xb[2];
    xa[0] = *(const ulonglong2*)(XA);
    xb[0] = *(const ulonglong2*)(XB);
    xa[1] = *(const ulonglong2*)(XA + rowb);
    xb[1] = *(const ulonglong2*)(XB + rowb);

    #pragma unroll 2
    for (int k = 0; k < NP; k++) {
        const int kp = (k + 2 < NP) ? (k + 2) : k;      // clamped prefetch row
        ulonglong2 na = *(const ulonglong2*)(XA + (size_t)kp * rowb);
        ulonglong2 nb = *(const ulonglong2*)(XB + (size_t)kp * rowb);

        ulonglong2 rv[4];
        #pragma unroll
        for (int u = 0; u < 4; u++) rv[u] = sR2[k * 32 + rbase + u];

        const ulonglong2 cA = xa[k & 1], cB = xb[k & 1];
        #pragma unroll
        for (int il = 0; il < 8; il++) {
            const u64 Rd = (il & 1) ? rv[il >> 1].y : rv[il >> 1].x;
            fma2(aA[il][0], Rd, cA.x);
            fma2(aA[il][1], Rd, cA.y);
            fma2(aB[il][0], Rd, cB.x);
            fma2(aB[il][1], Rd, cB.y);
        }
        xa[k & 1] = na;
        xb[k & 1] = nb;
    }

    #pragma unroll
    for (int il = 0; il < 8; il++) {
        const int i = wid * 8 + il;
        if (actA) {
            ulonglong2 v; v.x = aA[il][0]; v.y = aA[il][1];
            *(ulonglong2*)(out + (size_t)i * NCOLS + colA) = v;
        }
        if (actB) {
            ulonglong2 v; v.x = aB[il][0]; v.y = aB[il][1];
            *(ulonglong2*)(out + (size_t)i * NCOLS + colB) = v;
        }
    }
}

// ---------------------------------------------------------------------------
extern "C" void kernel_launch(void* const* d_in, const int* in_sizes, int n_in,
                              void* d_out, int out_size) {
    const float* X      = (const float*)d_in[0];
    const float* angles = (const float*)d_in[1];
    const float* mus    = (const float*)d_in[2];
    float*       out    = (float*)d_out;

    build_R_kernel<<<1, NP>>>(angles, mus);
    gemm_kernel<<<NB, 256>>>(X, out);
}